// round 1
// baseline (speedup 1.0000x reference)
#include <cuda_runtime.h>
#include <cstdint>

// Problem constants (fixed by the reference)
#define Bdim 128
#define Ndim 100000
#define Ddim 128
#define NTILE 64
#define NBLK ((Ndim + NTILE - 1) / NTILE)   // 1563
#define XS_PITCH 132                        // floats; mult of 4 (float4 align)
#define FS_PITCH 68                         // floats; mult of 4 (16B align)

// Scratch (no allocation allowed in kernel_launch)
__device__ float g_col0[Ndim];
__device__ float g_partial[Bdim * NBLK];
__device__ float g_invsum[Bdim];

// ---------------------------------------------------------------------------
// Pass 0: extract label column of memory_da into a compact array
// ---------------------------------------------------------------------------
__global__ void k_init(const float* __restrict__ mda) {
    int i = blockIdx.x * blockDim.x + threadIdx.x;
    if (i < Ndim) g_col0[i] = mda[(size_t)i * 129];
}

// ---------------------------------------------------------------------------
// Pass 1: out_unnorm[b][n] = exp(dot(x[b], feats[n]) / T); per-block partial
// row sums into g_partial (deterministic, no atomics).
// Block: 256 threads, computes a 128(b) x 64(n) tile. Thread micro-tile: 8b x 4n.
// f32x2 packed FMAs (n-paired accumulators).
// ---------------------------------------------------------------------------
__global__ void __launch_bounds__(256, 2)
k_gemm(const float* __restrict__ x, const float* __restrict__ mda,
       float* __restrict__ out) {
    extern __shared__ float sh[];
    float* xs = sh;                        // [128][XS_PITCH]   (b-major)
    float* fs = sh + Bdim * XS_PITCH;      // [128][FS_PITCH]   (k-major)

    const int tid  = threadIdx.x;
    const int w    = tid >> 5;
    const int lane = tid & 31;
    const int n_base = blockIdx.x * NTILE;

    // ---- stage x: straight copy with pitch change, fully coalesced ----
    {
        const float4* xv = reinterpret_cast<const float4*>(x);
        for (int i = tid; i < (Bdim * Ddim) / 4; i += 256) {
            float4 v = xv[i];
            int b  = i >> 5;        // 32 float4 per row
            int kq = i & 31;
            *reinterpret_cast<float4*>(&xs[b * XS_PITCH + kq * 4]) = v;
        }
    }

    // ---- stage feats transposed to k-major. warp w handles row nl per iter,
    //      lane covers k = 4*lane .. 4*lane+3 (2-way STS conflict, one-time) ----
    for (int it = 0; it < 8; ++it) {
        int nl = it * 8 + w;
        int n  = n_base + nl;
        const float* src = mda + (size_t)n * 129 + 1 + 4 * lane;
#pragma unroll
        for (int i = 0; i < 4; ++i) {
            float v = (n < Ndim) ? src[i] : 0.0f;
            fs[(4 * lane + i) * FS_PITCH + nl] = v;
        }
    }
    __syncthreads();

    // ---- register tiling ----
    const int ng  = tid & 15;          // n sub-tile (4 n's)
    const int bg  = tid >> 4;          // b group (8 b's)
    const int b0  = bg * 8;
    const int nl0 = ng * 4;
    const int xbase = b0 * XS_PITCH;

    unsigned long long acc[8][2];
#pragma unroll
    for (int i = 0; i < 8; ++i) { acc[i][0] = 0ull; acc[i][1] = 0ull; }

    for (int k = 0; k < Ddim; k += 4) {
        float4 xr[8];
#pragma unroll
        for (int i = 0; i < 8; ++i)
            xr[i] = *reinterpret_cast<const float4*>(&xs[xbase + i * XS_PITCH + k]);
#pragma unroll
        for (int j = 0; j < 4; ++j) {
            float4 fv = *reinterpret_cast<const float4*>(&fs[(k + j) * FS_PITCH + nl0]);
            unsigned long long f01, f23;
            asm("mov.b64 %0, {%1, %2};" : "=l"(f01) : "f"(fv.x), "f"(fv.y));
            asm("mov.b64 %0, {%1, %2};" : "=l"(f23) : "f"(fv.z), "f"(fv.w));
#pragma unroll
            for (int i = 0; i < 8; ++i) {
                float xv = (j == 0) ? xr[i].x : (j == 1) ? xr[i].y
                         : (j == 2) ? xr[i].z : xr[i].w;
                unsigned long long xx;
                asm("mov.b64 %0, {%1, %1};" : "=l"(xx) : "f"(xv));
                asm("fma.rn.f32x2 %0, %1, %2, %0;"
                    : "+l"(acc[i][0]) : "l"(xx), "l"(f01));
                asm("fma.rn.f32x2 %0, %1, %2, %0;"
                    : "+l"(acc[i][1]) : "l"(xx), "l"(f23));
            }
        }
    }

    // ---- epilogue: exp, store, partial row sums ----
    const float inv_t = 14.285714285714285714f;   // 1/0.07
    const int   n0    = n_base + nl0;
    const bool  valid = (n0 < Ndim);               // remainder is a multiple of 4

    float rsum[8];
#pragma unroll
    for (int i = 0; i < 8; ++i) {
        float v0, v1, v2, v3;
        asm("mov.b64 {%0, %1}, %2;" : "=f"(v0), "=f"(v1) : "l"(acc[i][0]));
        asm("mov.b64 {%0, %1}, %2;" : "=f"(v2), "=f"(v3) : "l"(acc[i][1]));
        float e0 = valid ? __expf(v0 * inv_t) : 0.0f;
        float e1 = valid ? __expf(v1 * inv_t) : 0.0f;
        float e2 = valid ? __expf(v2 * inv_t) : 0.0f;
        float e3 = valid ? __expf(v3 * inv_t) : 0.0f;
        if (valid) {
            float4 o = make_float4(e0, e1, e2, e3);
            *reinterpret_cast<float4*>(&out[(size_t)(b0 + i) * Ndim + n0]) = o;
        }
        rsum[i] = (e0 + e1) + (e2 + e3);
    }
#pragma unroll
    for (int i = 0; i < 8; ++i) {
#pragma unroll
        for (int o = 8; o > 0; o >>= 1)
            rsum[i] += __shfl_xor_sync(0xffffffffu, rsum[i], o);
    }
    if (ng == 0) {
#pragma unroll
        for (int i = 0; i < 8; ++i)
            g_partial[(size_t)(b0 + i) * NBLK + blockIdx.x] = rsum[i];
    }
}

// ---------------------------------------------------------------------------
// Pass 2: deterministic tree reduction of partials; stores 1/sum
// ---------------------------------------------------------------------------
__global__ void k_reduce() {
    __shared__ float sh[256];
    const int b = blockIdx.x, t = threadIdx.x;
    float s = 0.0f;
    for (int i = t; i < NBLK; i += 256) s += g_partial[(size_t)b * NBLK + i];
    sh[t] = s;
    __syncthreads();
    for (int o = 128; o > 0; o >>= 1) {
        if (t < o) sh[t] += sh[t + o];
        __syncthreads();
    }
    if (t == 0) g_invsum[b] = 1.0f / sh[0];
}

// ---------------------------------------------------------------------------
// Pass 3: normalize out in place, write mask. float4 throughout.
// grid: (ceil(N/4/256), B)
// ---------------------------------------------------------------------------
__global__ void __launch_bounds__(256)
k_norm(const int* __restrict__ labels, float* __restrict__ out) {
    const int b  = blockIdx.y;
    const int n  = (blockIdx.x * blockDim.x + threadIdx.x) * 4;
    if (n >= Ndim) return;

    const float inv = g_invsum[b];
    const float lab = (float)labels[b];

    float* orow = out + (size_t)b * Ndim;
    float4 v = *reinterpret_cast<const float4*>(&orow[n]);
    v.x *= inv; v.y *= inv; v.z *= inv; v.w *= inv;
    *reinterpret_cast<float4*>(&orow[n]) = v;

    float4 c = *reinterpret_cast<const float4*>(&g_col0[n]);
    float4 m = make_float4(c.x == lab ? 1.0f : 0.0f,
                           c.y == lab ? 1.0f : 0.0f,
                           c.z == lab ? 1.0f : 0.0f,
                           c.w == lab ? 1.0f : 0.0f);
    float* mrow = out + (size_t)Bdim * Ndim + (size_t)b * Ndim;
    *reinterpret_cast<float4*>(&mrow[n]) = m;
}

// ---------------------------------------------------------------------------
extern "C" void kernel_launch(void* const* d_in, const int* in_sizes, int n_in,
                              void* d_out, int out_size) {
    const float* x      = (const float*)d_in[0];   // [128,128]
    const int*   labels = (const int*)  d_in[2];   // [128]
    const float* mda    = (const float*)d_in[3];   // [100000,129]
    float*       out    = (float*)d_out;           // [out ; mask]

    const size_t smem = (size_t)(Bdim * XS_PITCH + Ddim * FS_PITCH) * sizeof(float);
    cudaFuncSetAttribute(k_gemm, cudaFuncAttributeMaxDynamicSharedMemorySize,
                         (int)smem);

    k_init<<<(Ndim + 255) / 256, 256>>>(mda);
    k_gemm<<<NBLK, 256, smem>>>(x, mda, out);
    k_reduce<<<Bdim, 256>>>();
    dim3 ngrid((Ndim / 4 + 255) / 256, Bdim);
    k_norm<<<ngrid, 256>>>(labels, out);
}

// round 3
// speedup vs baseline: 1.3043x; 1.3043x over previous
#include <cuda_runtime.h>
#include <cuda_bf16.h>
#include <cstdint>

// Problem constants
#define Bdim 128
#define Ndim 100000
#define Ddim 128
#define NT   64
#define NBLK ((Ndim + NT - 1) / NT)     // 1563
#define THREADS 256
#define INV_T 14.285714285714285714f

// smem layout (bytes). pitch 272B per row (128 bf16 = 256B + 16B pad)
#define PITCH  272
#define SM_AH  0
#define SM_AL  34816                     // 128*272
#define SM_BH  69632
#define SM_BL  87040                     // +64*272
#define SM_RACC 104448                   // 2*128 floats
#define SM_TOTAL 105472

// Scratch
__device__ float g_col0[Ndim];
__device__ float g_partial[Bdim * NBLK];
__device__ float g_invsum[Bdim];

// ---------------- helpers ----------------
__device__ __forceinline__ float bf16_rn_f(float v) {
    return __bfloat162float(__float2bfloat16_rn(v));
}
// pack two f32 into bf16x2: 'lo' element -> low 16 bits
__device__ __forceinline__ uint32_t pack2(float lo, float hi) {
    uint32_t r;
    asm("cvt.rn.bf16x2.f32 %0, %1, %2;" : "=r"(r) : "f"(hi), "f"(lo));
    return r;
}
__device__ __forceinline__ void mma_bf16(float* d, const uint32_t* a, const uint32_t* b) {
    asm volatile(
        "mma.sync.aligned.m16n8k16.row.col.f32.bf16.bf16.f32 "
        "{%0,%1,%2,%3}, {%4,%5,%6,%7}, {%8,%9}, {%0,%1,%2,%3};"
        : "+f"(d[0]), "+f"(d[1]), "+f"(d[2]), "+f"(d[3])
        : "r"(a[0]), "r"(a[1]), "r"(a[2]), "r"(a[3]), "r"(b[0]), "r"(b[1]));
}

// ---------------------------------------------------------------------------
// Pass 0: extract label column
// ---------------------------------------------------------------------------
__global__ void k_init(const float* __restrict__ mda) {
    int i = blockIdx.x * blockDim.x + threadIdx.x;
    if (i < Ndim) g_col0[i] = mda[(size_t)i * 129];
}

// ---------------------------------------------------------------------------
// Pass 1: bf16-split tensor GEMM (mma.sync) + exp + per-block row sums
// Block: 256 thr, tile 128(M) x 64(N). Warp grid 4(M) x 2(N), warp tile 32x32.
// ---------------------------------------------------------------------------
__global__ void __launch_bounds__(THREADS, 2)
k_gemm(const float* __restrict__ x, const float* __restrict__ mda,
       float* __restrict__ out) {
    extern __shared__ char smem[];
    const int tid  = threadIdx.x;
    const int wid  = tid >> 5;
    const int lane = tid & 31;
    const int n0   = blockIdx.x * NT;

    // ---- stage A = x (hi/lo bf16 split), float4 loads, bf16x2 stores ----
    {
        const float4* xv = reinterpret_cast<const float4*>(x);
        for (int i = tid; i < (Bdim * Ddim) / 4; i += THREADS) {
            float4 v = xv[i];
            int b = i >> 5, k = (i & 31) * 4;
            float hx = bf16_rn_f(v.x), hy = bf16_rn_f(v.y);
            float hz = bf16_rn_f(v.z), hw = bf16_rn_f(v.w);
            char* pa = smem + (size_t)b * PITCH + k * 2;
            *(uint32_t*)(pa + SM_AH)     = pack2(hx, hy);
            *(uint32_t*)(pa + SM_AH + 4) = pack2(hz, hw);
            *(uint32_t*)(pa + SM_AL)     = pack2(v.x - hx, v.y - hy);
            *(uint32_t*)(pa + SM_AL + 4) = pack2(v.z - hz, v.w - hw);
        }
    }

    // ---- stage B = feats tile (hi/lo), scalar loads (row base misaligned) ----
    {
#pragma unroll
        for (int j = 0; j < (NT * Ddim) / THREADS; ++j) {
            int e = tid + THREADS * j;
            int nl = e >> 7, k = e & 127;
            int n = n0 + nl;
            float v = (n < Ndim) ? __ldg(mda + (size_t)n * 129 + 1 + k) : 0.0f;
            float h = bf16_rn_f(v);
            char* pb = smem + (size_t)nl * PITCH + k * 2;
            *(__nv_bfloat16*)(pb + SM_BH) = __float2bfloat16_rn(h);
            *(__nv_bfloat16*)(pb + SM_BL) = __float2bfloat16_rn(v - h);
        }
    }
    __syncthreads();

    // ---- warp tiling ----
    const int wm = wid >> 1, wn = wid & 1;
    const int gid = lane >> 2, tg = lane & 3;

    const char* aB = smem + (size_t)(wm * 32 + gid) * PITCH + tg * 4;
    const char* bB = smem + (size_t)(wn * 32 + gid) * PITCH + tg * 4;

    float acc[2][4][4];
#pragma unroll
    for (int mi = 0; mi < 2; ++mi)
#pragma unroll
        for (int ni = 0; ni < 4; ++ni)
#pragma unroll
            for (int r = 0; r < 4; ++r) acc[mi][ni][r] = 0.0f;

#pragma unroll
    for (int ks = 0; ks < 8; ++ks) {
        const int ko = ks * 32;     // 16 k * 2 bytes
        uint32_t ah[2][4], al[2][4], bh[4][2], bl[4][2];
#pragma unroll
        for (int mi = 0; mi < 2; ++mi) {
            const char* p = aB + mi * (16 * PITCH) + ko;
            ah[mi][0] = *(const uint32_t*)(p + SM_AH);
            ah[mi][1] = *(const uint32_t*)(p + SM_AH + 8 * PITCH);
            ah[mi][2] = *(const uint32_t*)(p + SM_AH + 16);
            ah[mi][3] = *(const uint32_t*)(p + SM_AH + 8 * PITCH + 16);
            al[mi][0] = *(const uint32_t*)(p + SM_AL);
            al[mi][1] = *(const uint32_t*)(p + SM_AL + 8 * PITCH);
            al[mi][2] = *(const uint32_t*)(p + SM_AL + 16);
            al[mi][3] = *(const uint32_t*)(p + SM_AL + 8 * PITCH + 16);
        }
#pragma unroll
        for (int ni = 0; ni < 4; ++ni) {
            const char* p = bB + ni * (8 * PITCH) + ko;
            bh[ni][0] = *(const uint32_t*)(p + SM_BH);
            bh[ni][1] = *(const uint32_t*)(p + SM_BH + 16);
            bl[ni][0] = *(const uint32_t*)(p + SM_BL);
            bl[ni][1] = *(const uint32_t*)(p + SM_BL + 16);
        }
#pragma unroll
        for (int mi = 0; mi < 2; ++mi)
#pragma unroll
            for (int ni = 0; ni < 4; ++ni) {
                mma_bf16(acc[mi][ni], ah[mi], bh[ni]);
                mma_bf16(acc[mi][ni], al[mi], bh[ni]);
                mma_bf16(acc[mi][ni], ah[mi], bl[ni]);
            }
    }

    // ---- epilogue: exp, store, row partial sums ----
    float* racc = (float*)(smem + SM_RACC);
    float rs[2][2] = {{0.0f, 0.0f}, {0.0f, 0.0f}};
#pragma unroll
    for (int mi = 0; mi < 2; ++mi) {
        const int m_lo = wm * 32 + mi * 16 + gid;
#pragma unroll
        for (int ni = 0; ni < 4; ++ni) {
            const int ng = n0 + wn * 32 + ni * 8 + tg * 2;
            const bool ok = ng < Ndim;
            float e0 = ok ? __expf(acc[mi][ni][0] * INV_T) : 0.0f;
            float e1 = ok ? __expf(acc[mi][ni][1] * INV_T) : 0.0f;
            float e2 = ok ? __expf(acc[mi][ni][2] * INV_T) : 0.0f;
            float e3 = ok ? __expf(acc[mi][ni][3] * INV_T) : 0.0f;
            if (ok) {
                *(float2*)(out + (size_t)m_lo * Ndim + ng)       = make_float2(e0, e1);
                *(float2*)(out + (size_t)(m_lo + 8) * Ndim + ng) = make_float2(e2, e3);
            }
            rs[mi][0] += e0 + e1;
            rs[mi][1] += e2 + e3;
        }
    }
#pragma unroll
    for (int mi = 0; mi < 2; ++mi) {
#pragma unroll
        for (int o = 1; o <= 2; o <<= 1) {
            rs[mi][0] += __shfl_xor_sync(0xffffffffu, rs[mi][0], o);
            rs[mi][1] += __shfl_xor_sync(0xffffffffu, rs[mi][1], o);
        }
        if (tg == 0) {
            const int m_lo = wm * 32 + mi * 16 + gid;
            racc[wn * 128 + m_lo]     = rs[mi][0];
            racc[wn * 128 + m_lo + 8] = rs[mi][1];
        }
    }
    __syncthreads();
    if (tid < 128)
        g_partial[(size_t)tid * NBLK + blockIdx.x] = racc[tid] + racc[128 + tid];
}

// ---------------------------------------------------------------------------
// Pass 2: deterministic reduction of per-block partials
// ---------------------------------------------------------------------------
__global__ void k_reduce() {
    __shared__ float sh[256];
    const int b = blockIdx.x, t = threadIdx.x;
    float s = 0.0f;
    for (int i = t; i < NBLK; i += 256) s += g_partial[(size_t)b * NBLK + i];
    sh[t] = s;
    __syncthreads();
    for (int o = 128; o > 0; o >>= 1) {
        if (t < o) sh[t] += sh[t + o];
        __syncthreads();
    }
    if (t == 0) g_invsum[b] = 1.0f / sh[0];
}

// ---------------------------------------------------------------------------
// Pass 3: normalize + mask, batched float4 loads for MLP
// ---------------------------------------------------------------------------
__global__ void __launch_bounds__(256)
k_norm(const int* __restrict__ labels, float* __restrict__ out) {
    const int b = blockIdx.y;
    const float inv = g_invsum[b];
    const float lab = (float)labels[b];
    const int f0 = blockIdx.x * 1024 + threadIdx.x;
    const int NF4 = Ndim / 4;

    float4* orow = reinterpret_cast<float4*>(out + (size_t)b * Ndim);
    float4* mrow = reinterpret_cast<float4*>(out + (size_t)Bdim * Ndim + (size_t)b * Ndim);
    const float4* c4 = reinterpret_cast<const float4*>(g_col0);

    float4 v[4], c[4];
    bool ok[4];
#pragma unroll
    for (int j = 0; j < 4; ++j) {
        int f = f0 + 256 * j;
        ok[j] = f < NF4;
        if (ok[j]) { v[j] = orow[f]; c[j] = c4[f]; }
    }
#pragma unroll
    for (int j = 0; j < 4; ++j) {
        if (!ok[j]) continue;
        int f = f0 + 256 * j;
        float4 t = v[j];
        t.x *= inv; t.y *= inv; t.z *= inv; t.w *= inv;
        orow[f] = t;
        float4 cc = c[j];
        mrow[f] = make_float4(cc.x == lab ? 1.0f : 0.0f, cc.y == lab ? 1.0f : 0.0f,
                              cc.z == lab ? 1.0f : 0.0f, cc.w == lab ? 1.0f : 0.0f);
    }
}

// ---------------------------------------------------------------------------
extern "C" void kernel_launch(void* const* d_in, const int* in_sizes, int n_in,
                              void* d_out, int out_size) {
    const float* x      = (const float*)d_in[0];   // [128,128]
    const int*   labels = (const int*)  d_in[2];   // [128]
    const float* mda    = (const float*)d_in[3];   // [100000,129]
    float*       out    = (float*)d_out;

    cudaFuncSetAttribute(k_gemm, cudaFuncAttributeMaxDynamicSharedMemorySize, SM_TOTAL);

    k_init<<<(Ndim + 255) / 256, 256>>>(mda);
    k_gemm<<<NBLK, THREADS, SM_TOTAL>>>(x, mda, out);
    k_reduce<<<Bdim, 256>>>();
    dim3 ngrid((Ndim / 4 + 1023) / 1024, Bdim);
    k_norm<<<ngrid, 256>>>(labels, out);
}

// round 4
// speedup vs baseline: 1.7419x; 1.3356x over previous
#include <cuda_runtime.h>
#include <cuda_fp16.h>
#include <cstdint>

// Problem constants
#define Bdim 128
#define Ndim 100000
#define Ddim 128
#define NT   64
#define NBLK ((Ndim + NT - 1) / NT)     // 1563
#define THREADS 256
#define INV_T 14.285714285714285714f

// smem layout (bytes). pitch 272B per row (128 fp16 = 256B + 16B pad)
#define PITCH  272
#define SM_AH  0
#define SM_AL  34816                     // +128*272
#define SM_B   69632                     // +128*272 (B uses 64 rows = 17408)
#define SM_RACC 87040                    // 2*128 floats
#define SM_TOTAL 88064

// Scratch
__device__ float g_partial[Bdim * NBLK];
__device__ float g_invsum[Bdim];

// ---------------- helpers ----------------
__device__ __forceinline__ float f16_rn_f(float v) {
    return __half2float(__float2half_rn(v));
}
// pack two f32 into f16x2: first arg -> low 16 bits
__device__ __forceinline__ uint32_t pack2(float lo, float hi) {
    uint32_t r;
    asm("cvt.rn.f16x2.f32 %0, %1, %2;" : "=r"(r) : "f"(hi), "f"(lo));
    return r;
}
__device__ __forceinline__ void mma_f16(float* d, const uint32_t* a, const uint32_t* b) {
    asm volatile(
        "mma.sync.aligned.m16n8k16.row.col.f32.f16.f16.f32 "
        "{%0,%1,%2,%3}, {%4,%5,%6,%7}, {%8,%9}, {%0,%1,%2,%3};"
        : "+f"(d[0]), "+f"(d[1]), "+f"(d[2]), "+f"(d[3])
        : "r"(a[0]), "r"(a[1]), "r"(a[2]), "r"(a[3]), "r"(b[0]), "r"(b[1]));
}

// ---------------------------------------------------------------------------
// Pass 1: fp16-split tensor GEMM (mma.sync, 2 passes) + exp + row sums + mask
// Block: 256 thr, tile 128(M) x 64(N). Warp grid 4(M) x 2(N), warp tile 32x32.
// ---------------------------------------------------------------------------
__global__ void __launch_bounds__(THREADS, 2)
k_gemm(const float* __restrict__ x, const float* __restrict__ mda,
       const int* __restrict__ labels, float* __restrict__ out) {
    extern __shared__ char smem[];
    const int tid  = threadIdx.x;
    const int wid  = tid >> 5;
    const int lane = tid & 31;
    const int n0   = blockIdx.x * NT;

    // ---- stage A = x (hi/lo fp16 split), float4 loads ----
    {
        const float4* xv = reinterpret_cast<const float4*>(x);
        for (int i = tid; i < (Bdim * Ddim) / 4; i += THREADS) {
            float4 v = xv[i];
            int b = i >> 5, k = (i & 31) * 4;
            float hx = f16_rn_f(v.x), hy = f16_rn_f(v.y);
            float hz = f16_rn_f(v.z), hw = f16_rn_f(v.w);
            char* pa = smem + (size_t)b * PITCH + k * 2;
            *(uint32_t*)(pa + SM_AH)     = pack2(hx, hy);
            *(uint32_t*)(pa + SM_AH + 4) = pack2(hz, hw);
            *(uint32_t*)(pa + SM_AL)     = pack2(v.x - hx, v.y - hy);
            *(uint32_t*)(pa + SM_AL + 4) = pack2(v.z - hz, v.w - hw);
        }
    }

    // ---- stage B = feats tile (single fp16), streaming loads ----
    {
#pragma unroll
        for (int j = 0; j < (NT * Ddim) / THREADS; ++j) {
            int e = tid + THREADS * j;
            int nl = e >> 7, k = e & 127;
            int n = n0 + nl;
            float v = (n < Ndim) ? __ldcs(mda + (size_t)n * 129 + 1 + k) : 0.0f;
            *(__half*)(smem + SM_B + (size_t)nl * PITCH + k * 2) = __float2half_rn(v);
        }
    }
    __syncthreads();

    // ---- warp tiling ----
    const int wm = wid >> 1, wn = wid & 1;
    const int gid = lane >> 2, tg = lane & 3;

    const char* aB = smem + (size_t)(wm * 32 + gid) * PITCH + tg * 4;
    const char* bB = smem + (size_t)(wn * 32 + gid) * PITCH + tg * 4;

    float acc[2][4][4];
#pragma unroll
    for (int mi = 0; mi < 2; ++mi)
#pragma unroll
        for (int ni = 0; ni < 4; ++ni)
#pragma unroll
            for (int r = 0; r < 4; ++r) acc[mi][ni][r] = 0.0f;

#pragma unroll
    for (int ks = 0; ks < 8; ++ks) {
        const int ko = ks * 32;     // 16 k * 2 bytes
        uint32_t ah[2][4], al[2][4], bh[4][2];
#pragma unroll
        for (int mi = 0; mi < 2; ++mi) {
            const char* p = aB + mi * (16 * PITCH) + ko;
            ah[mi][0] = *(const uint32_t*)(p + SM_AH);
            ah[mi][1] = *(const uint32_t*)(p + SM_AH + 8 * PITCH);
            ah[mi][2] = *(const uint32_t*)(p + SM_AH + 16);
            ah[mi][3] = *(const uint32_t*)(p + SM_AH + 8 * PITCH + 16);
            al[mi][0] = *(const uint32_t*)(p + SM_AL);
            al[mi][1] = *(const uint32_t*)(p + SM_AL + 8 * PITCH);
            al[mi][2] = *(const uint32_t*)(p + SM_AL + 16);
            al[mi][3] = *(const uint32_t*)(p + SM_AL + 8 * PITCH + 16);
        }
#pragma unroll
        for (int ni = 0; ni < 4; ++ni) {
            const char* p = bB + ni * (8 * PITCH) + ko;
            bh[ni][0] = *(const uint32_t*)(p + SM_B);
            bh[ni][1] = *(const uint32_t*)(p + SM_B + 16);
        }
#pragma unroll
        for (int mi = 0; mi < 2; ++mi)
#pragma unroll
            for (int ni = 0; ni < 4; ++ni) {
                mma_f16(acc[mi][ni], ah[mi], bh[ni]);
                mma_f16(acc[mi][ni], al[mi], bh[ni]);
            }
    }

    // ---- epilogue: exp, store, row partial sums ----
    float* racc = (float*)(smem + SM_RACC);
    float rs[2][2] = {{0.0f, 0.0f}, {0.0f, 0.0f}};
#pragma unroll
    for (int mi = 0; mi < 2; ++mi) {
        const int m_lo = wm * 32 + mi * 16 + gid;
#pragma unroll
        for (int ni = 0; ni < 4; ++ni) {
            const int ng = n0 + wn * 32 + ni * 8 + tg * 2;
            const bool ok = ng < Ndim;              // Ndim even -> pair guard
            float e0 = ok ? __expf(acc[mi][ni][0] * INV_T) : 0.0f;
            float e1 = ok ? __expf(acc[mi][ni][1] * INV_T) : 0.0f;
            float e2 = ok ? __expf(acc[mi][ni][2] * INV_T) : 0.0f;
            float e3 = ok ? __expf(acc[mi][ni][3] * INV_T) : 0.0f;
            if (ok) {
                *(float2*)(out + (size_t)m_lo * Ndim + ng)       = make_float2(e0, e1);
                *(float2*)(out + (size_t)(m_lo + 8) * Ndim + ng) = make_float2(e2, e3);
            }
            rs[mi][0] += e0 + e1;
            rs[mi][1] += e2 + e3;
        }
    }

    // ---- mask write (independent of Z): m[b][n] = (mda[n*129] == label[b]) ----
    {
        const int n = n0 + lane * 2;
        if (n + 1 < Ndim) {
            float c0 = __ldg(mda + (size_t)n * 129);
            float c1 = __ldg(mda + (size_t)(n + 1) * 129);
            float* mbase = out + (size_t)Bdim * Ndim;
#pragma unroll
            for (int r = 0; r < 16; ++r) {
                const int b = wid + r * 8;
                const float lb = (float)__ldg(labels + b);
                float2 m = make_float2(c0 == lb ? 1.0f : 0.0f,
                                       c1 == lb ? 1.0f : 0.0f);
                __stcs((float2*)(mbase + (size_t)b * Ndim + n), m);
            }
        }
    }

#pragma unroll
    for (int mi = 0; mi < 2; ++mi) {
#pragma unroll
        for (int o = 1; o <= 2; o <<= 1) {
            rs[mi][0] += __shfl_xor_sync(0xffffffffu, rs[mi][0], o);
            rs[mi][1] += __shfl_xor_sync(0xffffffffu, rs[mi][1], o);
        }
        if (tg == 0) {
            const int m_lo = wm * 32 + mi * 16 + gid;
            racc[wn * 128 + m_lo]     = rs[mi][0];
            racc[wn * 128 + m_lo + 8] = rs[mi][1];
        }
    }
    __syncthreads();
    if (tid < 128)
        g_partial[(size_t)tid * NBLK + blockIdx.x] = racc[tid] + racc[128 + tid];
}

// ---------------------------------------------------------------------------
// Pass 2: deterministic reduction of per-block partials
// ---------------------------------------------------------------------------
__global__ void k_reduce() {
    __shared__ float sh[256];
    const int b = blockIdx.x, t = threadIdx.x;
    float s = 0.0f;
    for (int i = t; i < NBLK; i += 256) s += g_partial[(size_t)b * NBLK + i];
    sh[t] = s;
    __syncthreads();
    for (int o = 128; o > 0; o >>= 1) {
        if (t < o) sh[t] += sh[t + o];
        __syncthreads();
    }
    if (t == 0) g_invsum[b] = 1.0f / sh[0];
}

// ---------------------------------------------------------------------------
// Pass 3: in-place normalize only (mask already written by k_gemm)
// ---------------------------------------------------------------------------
__global__ void __launch_bounds__(256)
k_norm(float* __restrict__ out) {
    const int b = blockIdx.y;
    const float inv = g_invsum[b];
    const int f0 = blockIdx.x * 1024 + threadIdx.x;
    const int NF4 = Ndim / 4;

    float4* orow = reinterpret_cast<float4*>(out + (size_t)b * Ndim);

    float4 v[4];
    bool ok[4];
#pragma unroll
    for (int j = 0; j < 4; ++j) {
        int f = f0 + 256 * j;
        ok[j] = f < NF4;
        if (ok[j]) v[j] = orow[f];
    }
#pragma unroll
    for (int j = 0; j < 4; ++j) {
        if (!ok[j]) continue;
        int f = f0 + 256 * j;
        float4 t = v[j];
        t.x *= inv; t.y *= inv; t.z *= inv; t.w *= inv;
        orow[f] = t;
    }
}

// ---------------------------------------------------------------------------
extern "C" void kernel_launch(void* const* d_in, const int* in_sizes, int n_in,
                              void* d_out, int out_size) {
    const float* x      = (const float*)d_in[0];   // [128,128]
    const int*   labels = (const int*)  d_in[2];   // [128]
    const float* mda    = (const float*)d_in[3];   // [100000,129]
    float*       out    = (float*)d_out;

    cudaFuncSetAttribute(k_gemm, cudaFuncAttributeMaxDynamicSharedMemorySize, SM_TOTAL);

    k_gemm<<<NBLK, THREADS, SM_TOTAL>>>(x, mda, labels, out);
    k_reduce<<<Bdim, 256>>>();
    dim3 ngrid((Ndim / 4 + 1023) / 1024, Bdim);
    k_norm<<<ngrid, 256>>>(out);
}